// round 14
// baseline (speedup 1.0000x reference)
#include <cuda_runtime.h>
#include <cuda_bf16.h>
#include <cstdint>

// MPNN, B=4096 graphs, N=64, D=128, L=3. One graph per CTA (M=64), 2 CTAs/SM.
// Algebra: z2 = relu((I+adj)(z1 W2^T) + b2) with Y1 = z1 W2^T per fingerprint:
//   stage A: D = adjI @ Y1g (K=64)   -> z2 = relu(D + b2)   [z2 -> AH region]
//   stage B: h3 = adjI @ z2 (K=64)                          [h3 -> AH, overwrite]
//   stage C: D3 = h3 @ W3^T (K=128)  -> pooled epilogue:
//            out[k] = sum_m w_m relu(D3[m,k]+b3[k]), w = 1 + colsum(adj)
// fp32 = hi + lo (bf16, truncated hi); 3 HMMA passes hi*hi + hi*lo + lo*hi.
// Pipelining: W3-upper prefetched at start; W3-lower issued the moment Y1g
// dies (post stage A) and hides under z2-epi + stage B.

__device__ __align__(16) unsigned short g_w3_hi[16384];      // W3 [128r][16ch] swizzled
__device__ __align__(16) unsigned short g_w3_lo[16384];
__device__ __align__(16) unsigned short g_y1_hi[2048 * 128]; // Y1 row-major [fp][k]
__device__ __align__(16) unsigned short g_y1_lo[2048 * 128];

// ---- main-kernel smem layout (112KB / CTA -> 2 CTAs/SM) ----
#define SM_AH     0         // colsum scratch -> z2 -> h3   [64][256B] hi
#define SM_AH_LO  16384
#define SM_WZ     32768     // lower 16KB: Y1g -> W3-lower ; upper 16KB: W3-upper
#define SM_WZ_LO  65536
#define SM_ADJ    98304     // adjI hi [64][128B] 8KB (pool scratch at the end)
#define SM_ADJ_LO 106496
#define SM_TOTAL  114688

// ---- fused-prologue smem layout (fp32 floats) ----
#define FP_SW   0                         // W tile [128][132]
#define FP_SX   (128 * 132)               // in rows [16][132]
#define FP_SZ   (FP_SX + 16 * 132)        // z rows  [16][132]
#define FP_SB   (FP_SZ + 16 * 132)        // bias 128 floats
#define FP_TOT  ((FP_SB + 128) * 4)

__device__ __forceinline__ uint32_t smem_u32(const void* p) {
    uint32_t a;
    asm("{ .reg .u64 t; cvta.to.shared.u64 t, %1; cvt.u32.u64 %0, t; }" : "=r"(a) : "l"(p));
    return a;
}
__device__ __forceinline__ void cp16(uint32_t dst, const void* src) {
    asm volatile("cp.async.cg.shared.global [%0], [%1], 16;" :: "r"(dst), "l"(src));
}
#define CP_COMMIT() asm volatile("cp.async.commit_group;" ::: "memory")
#define CP_WAIT0()  asm volatile("cp.async.wait_group 0;" ::: "memory")

__device__ __forceinline__ void ldsm4(uint32_t* r, uint32_t a) {
    asm volatile("ldmatrix.sync.aligned.m8n8.x4.shared.b16 {%0,%1,%2,%3}, [%4];"
                 : "=r"(r[0]), "=r"(r[1]), "=r"(r[2]), "=r"(r[3]) : "r"(a));
}
__device__ __forceinline__ void ldsm4t(uint32_t* r, uint32_t a) {
    asm volatile("ldmatrix.sync.aligned.m8n8.x4.trans.shared.b16 {%0,%1,%2,%3}, [%4];"
                 : "=r"(r[0]), "=r"(r[1]), "=r"(r[2]), "=r"(r[3]) : "r"(a));
}
__device__ __forceinline__ void mma16816(float* c, const uint32_t* a, const uint32_t* b) {
    asm volatile("mma.sync.aligned.m16n8k16.row.col.f32.bf16.bf16.f32 "
                 "{%0,%1,%2,%3}, {%4,%5,%6,%7}, {%8,%9}, {%0,%1,%2,%3};"
                 : "+f"(c[0]), "+f"(c[1]), "+f"(c[2]), "+f"(c[3])
                 : "r"(a[0]), "r"(a[1]), "r"(a[2]), "r"(a[3]), "r"(b[0]), "r"(b[1]));
}
__device__ __forceinline__ void pack_split(float v0, float v1, uint32_t& hi2, uint32_t& lo2) {
    uint32_t b0 = __float_as_uint(v0), b1 = __float_as_uint(v1);
    asm("prmt.b32 %0, %1, %2, 0x7632;" : "=r"(hi2) : "r"(b0), "r"(b1));
    float r0 = v0 - __uint_as_float(b0 & 0xffff0000u);
    float r1 = v1 - __uint_as_float(b1 & 0xffff0000u);
    asm("cvt.rn.bf16x2.f32 %0, %1, %2;" : "=r"(lo2) : "f"(r1), "f"(r0));
}
__device__ __forceinline__ int swz256(int row, int col) {
    return (row << 8) + ((((col >> 3) ^ (row & 7)) << 4) | ((col & 7) << 1));
}

// GEMM1: C[64x128] = h[64x128] @ W[128x128]^T ; warp tile 32x32, K=128
__device__ __forceinline__ void gemm1(float (&acc)[32], uint32_t aHi, uint32_t aLo,
                                      uint32_t bHi, uint32_t bLo,
                                      int m_base, int n_base, int lane) {
    #pragma unroll
    for (int i = 0; i < 32; i++) acc[i] = 0.0f;
    const int a_row = lane & 15, a_kc = lane >> 4;
    const int b_row = ((lane >> 4) << 3) + (lane & 7), b_kc = (lane >> 3) & 1;
    #pragma unroll
    for (int ks = 0; ks < 8; ks++) {
        uint32_t aH[2][4], aL[2][4];
        #pragma unroll
        for (int t = 0; t < 2; t++) {
            int row = m_base + t * 16 + a_row;
            uint32_t off = (row << 8) + ((((ks << 1) + a_kc) ^ (row & 7)) << 4);
            ldsm4(aH[t], aHi + off);
            ldsm4(aL[t], aLo + off);
        }
        #pragma unroll
        for (int p = 0; p < 2; p++) {
            int row = n_base + p * 16 + b_row;
            uint32_t off = (row << 8) + ((((ks << 1) + b_kc) ^ (row & 7)) << 4);
            uint32_t bH[4], bL[4];
            ldsm4(bH, bHi + off);
            ldsm4(bL, bLo + off);
            #pragma unroll
            for (int t = 0; t < 2; t++)
                #pragma unroll
                for (int s = 0; s < 2; s++) {
                    float* c = &acc[(t * 4 + p * 2 + s) * 4];
                    mma16816(c, aH[t], &bH[2 * s]);
                    mma16816(c, aH[t], &bL[2 * s]);
                    mma16816(c, aL[t], &bH[2 * s]);
                }
        }
    }
}

// GEMM2: C[64x128] = adjI[64x64] @ z[64x128]; A stride 128B, B via ldmatrix.trans
__device__ __forceinline__ void gemm2(float (&acc)[32], uint32_t aHi, uint32_t aLo,
                                      uint32_t zHi, uint32_t zLo,
                                      int m_base, int n_base, int lane) {
    #pragma unroll
    for (int i = 0; i < 32; i++) acc[i] = 0.0f;
    const int a_row = lane & 15, a_kc = lane >> 4;
    const int grp = lane >> 3, r = lane & 7;
    #pragma unroll
    for (int ks = 0; ks < 4; ks++) {
        uint32_t aH[2][4], aL[2][4];
        #pragma unroll
        for (int t = 0; t < 2; t++) {
            int row = m_base + t * 16 + a_row;
            uint32_t off = (row << 7) + ((((ks << 1) + a_kc) ^ (row & 7)) << 4);
            ldsm4(aH[t], aHi + off);
            ldsm4(aL[t], aLo + off);
        }
        int row_b = (ks << 4) + ((grp & 1) << 3) + r;
        #pragma unroll
        for (int p = 0; p < 2; p++) {
            int cc = ((n_base + p * 16) >> 3) + (grp >> 1);
            uint32_t off = (row_b << 8) + ((cc ^ (row_b & 7)) << 4);
            uint32_t bH[4], bL[4];
            ldsm4t(bH, zHi + off);
            ldsm4t(bL, zLo + off);
            #pragma unroll
            for (int t = 0; t < 2; t++)
                #pragma unroll
                for (int s = 0; s < 2; s++) {
                    float* c = &acc[(t * 4 + p * 2 + s) * 4];
                    mma16816(c, aH[t], &bH[2 * s]);
                    mma16816(c, aH[t], &bL[2 * s]);
                    mma16816(c, aL[t], &bH[2 * s]);
                }
        }
    }
}

// ---------------- fused prologue (unchanged from round 13 / passing) ----------------
__global__ __launch_bounds__(256)
void prep_all(const float* __restrict__ emb, const float* __restrict__ W,
              const float* __restrict__ bias) {
    const int tid = threadIdx.x;
    if (blockIdx.x >= 128) {
        int idx = (int)(blockIdx.x - 128) * 256 + tid;   // 0..16383
        int row = idx >> 7, col = idx & 127;
        float v = W[2 * 16384 + idx];
        uint32_t b = __float_as_uint(v);
        float lo = v - __uint_as_float(b & 0xffff0000u);
        int pos = row * 128 + (((col >> 3) ^ (row & 7)) << 3) + (col & 7);
        g_w3_hi[pos] = (unsigned short)(b >> 16);
        g_w3_lo[pos] = __bfloat16_as_ushort(__float2bfloat16(lo));
        return;
    }

    extern __shared__ float fsm[];
    float* sW = fsm + FP_SW;
    float* sX = fsm + FP_SX;
    float* sZ = fsm + FP_SZ;
    float* sB = fsm + FP_SB;
    const int tx = tid & 31, ty = tid >> 5;
    const int r0 = (int)blockIdx.x * 16;

    const float4* W4 = reinterpret_cast<const float4*>(W);
    #pragma unroll
    for (int i = 0; i < 16; i++) {
        int q = tid + (i << 8);
        int k = q >> 5, c4 = (q & 31) << 2;
        *reinterpret_cast<float4*>(&sW[k * 132 + c4]) = __ldg(W4 + q);
    }
    const float4* E4 = reinterpret_cast<const float4*>(emb);
    #pragma unroll
    for (int i = 0; i < 2; i++) {
        int q = tid + (i << 8);
        int r = q >> 5, c4 = (q & 31) << 2;
        *reinterpret_cast<float4*>(&sX[r * 132 + c4]) =
            __ldg(E4 + (size_t)(r0 + r) * 32 + (q & 31));
    }
    if (tid < 128) sB[tid] = bias[tid];
    __syncthreads();

    float acc[2][4];
    #pragma unroll
    for (int i = 0; i < 2; i++)
        #pragma unroll
        for (int j = 0; j < 4; j++) acc[i][j] = 0.0f;
    for (int d4 = 0; d4 < 32; d4++) {
        float4 wv[4], ev[2];
        #pragma unroll
        for (int j = 0; j < 4; j++)
            wv[j] = *reinterpret_cast<const float4*>(&sW[(tx + 32 * j) * 132 + (d4 << 2)]);
        #pragma unroll
        for (int i = 0; i < 2; i++)
            ev[i] = *reinterpret_cast<const float4*>(&sX[(ty * 2 + i) * 132 + (d4 << 2)]);
        #pragma unroll
        for (int i = 0; i < 2; i++)
            #pragma unroll
            for (int j = 0; j < 4; j++) {
                acc[i][j] = fmaf(ev[i].x, wv[j].x, acc[i][j]);
                acc[i][j] = fmaf(ev[i].y, wv[j].y, acc[i][j]);
                acc[i][j] = fmaf(ev[i].z, wv[j].z, acc[i][j]);
                acc[i][j] = fmaf(ev[i].w, wv[j].w, acc[i][j]);
            }
    }
    #pragma unroll
    for (int i = 0; i < 2; i++)
        #pragma unroll
        for (int j = 0; j < 4; j++) {
            int k = tx + 32 * j;
            sZ[(ty * 2 + i) * 132 + k] = fmaxf(acc[i][j] + sB[k], 0.0f);
        }
    __syncthreads();

    #pragma unroll
    for (int i = 0; i < 16; i++) {
        int q = tid + (i << 8);
        int k = q >> 5, c4 = (q & 31) << 2;
        *reinterpret_cast<float4*>(&sW[k * 132 + c4]) = __ldg(W4 + 4096 + q);
    }
    __syncthreads();

    #pragma unroll
    for (int i = 0; i < 2; i++)
        #pragma unroll
        for (int j = 0; j < 4; j++) acc[i][j] = 0.0f;
    for (int d4 = 0; d4 < 32; d4++) {
        float4 wv[4], ev[2];
        #pragma unroll
        for (int j = 0; j < 4; j++)
            wv[j] = *reinterpret_cast<const float4*>(&sW[(tx + 32 * j) * 132 + (d4 << 2)]);
        #pragma unroll
        for (int i = 0; i < 2; i++)
            ev[i] = *reinterpret_cast<const float4*>(&sZ[(ty * 2 + i) * 132 + (d4 << 2)]);
        #pragma unroll
        for (int i = 0; i < 2; i++)
            #pragma unroll
            for (int j = 0; j < 4; j++) {
                acc[i][j] = fmaf(ev[i].x, wv[j].x, acc[i][j]);
                acc[i][j] = fmaf(ev[i].y, wv[j].y, acc[i][j]);
                acc[i][j] = fmaf(ev[i].z, wv[j].z, acc[i][j]);
                acc[i][j] = fmaf(ev[i].w, wv[j].w, acc[i][j]);
            }
    }
    #pragma unroll
    for (int i = 0; i < 2; i++)
        #pragma unroll
        for (int j = 0; j < 4; j++) {
            int r = r0 + ty * 2 + i;
            int k = tx + 32 * j;
            float s = acc[i][j];
            uint32_t b = __float_as_uint(s);
            float lo = s - __uint_as_float(b & 0xffff0000u);
            g_y1_hi[r * 128 + k] = (unsigned short)(b >> 16);
            g_y1_lo[r * 128 + k] = __bfloat16_as_ushort(__float2bfloat16(lo));
        }
}

// ---------------- main kernel (restructured pipeline) ----------------
__global__ __launch_bounds__(256, 2)
void mpnn_main(const int* __restrict__ fps,
               const float* __restrict__ adj,
               const float* __restrict__ bias,
               float* __restrict__ out)
{
    extern __shared__ char smem[];
    const uint32_t sb = smem_u32(smem);
    const int tid = threadIdx.x, wid = tid >> 5, lane = tid & 31;
    const int bid = blockIdx.x;
    const int m_base = (wid & 1) << 5;     // 0 / 32
    const int n_base = (wid >> 1) << 5;    // 0,32,64,96

    // ---- issue Y1 gather into WZ LOWER + W3-upper into WZ UPPER ----
    #pragma unroll
    for (int i = 0; i < 8; i++) {
        int idx = tid + (i << 8);                  // 0..2047
        int buf = idx >> 10, rem = idx & 1023;
        int m = rem >> 4, c = rem & 15;
        int fp = fps[(bid << 6) + m];
        const unsigned short* src = (buf ? g_y1_lo : g_y1_hi) + (size_t)fp * 128 + c * 8;
        cp16(sb + SM_WZ + buf * 32768 + (m << 8) + ((c ^ (m & 7)) << 4), src);
    }
    #pragma unroll
    for (int i = 0; i < 8; i++) {
        int idx = tid + (i << 8);                  // W3 rows 64-127
        int buf = idx >> 10, rem = idx & 1023;
        const unsigned short* src = (buf ? g_w3_lo : g_w3_hi) + 8192 + rem * 8;
        cp16(sb + SM_WZ + buf * 32768 + 16384 + rem * 16, src);
    }
    CP_COMMIT();

    // ---- adjI = I + adj: split + swizzled STS + column-sum partials ----
    float4 s4 = make_float4(0.f, 0.f, 0.f, 0.f);
    {
        const float4* ag = reinterpret_cast<const float4*>(adj) + (size_t)bid * 1024;
        #pragma unroll
        for (int i = 0; i < 4; i++) {
            int q   = tid + (i << 8);              // float4 idx 0..1023
            int row = q >> 4;
            int c4  = (q & 15) << 2;
            float4 v = ag[q];
            float a0 = v.x + ((row == c4 + 0) ? 1.0f : 0.0f);
            float a1 = v.y + ((row == c4 + 1) ? 1.0f : 0.0f);
            float a2 = v.z + ((row == c4 + 2) ? 1.0f : 0.0f);
            float a3 = v.w + ((row == c4 + 3) ? 1.0f : 0.0f);
            s4.x += a0; s4.y += a1; s4.z += a2; s4.w += a3;
            uint32_t h0, l0, h1, l1;
            pack_split(a0, a1, h0, l0);
            pack_split(a2, a3, h1, l1);
            int off = (row << 7) + ((((c4 >> 3) ^ (row & 7)) << 4) | ((c4 & 7) << 1));
            *reinterpret_cast<uint32_t*>(smem + SM_ADJ + off)        = h0;
            *reinterpret_cast<uint32_t*>(smem + SM_ADJ + off + 4)    = h1;
            *reinterpret_cast<uint32_t*>(smem + SM_ADJ_LO + off)     = l0;
            *reinterpret_cast<uint32_t*>(smem + SM_ADJ_LO + off + 4) = l1;
        }
    }
    {   // colsum partials -> AH scratch (AH dead until z2 epilogue)
        float4* part = reinterpret_cast<float4*>(smem + SM_AH);
        part[tid] = s4;
    }
    __syncthreads();
    if (tid < 16) {
        float4* part = reinterpret_cast<float4*>(smem + SM_AH);
        float4 cs = part[tid];
        #pragma unroll
        for (int j = 1; j < 16; j++) {
            float4 p = part[tid + 16 * j];
            cs.x += p.x; cs.y += p.y; cs.z += p.z; cs.w += p.w;
        }
        *reinterpret_cast<float4*>(smem + SM_AH + 4096 + tid * 16) = cs;
    }
    CP_WAIT0();            // Y1g + W3-upper arrived
    __syncthreads();

    // cache pooling weights w[m] = 1 + colsum(adj)[m]
    // (no barrier needed after: first AH overwrite is the z2 epilogue, which is
    //  ordered behind the post-stage-A __syncthreads that every wreg read precedes)
    float wreg[4];
    {
        const float* wsm = reinterpret_cast<const float*>(smem + SM_AH + 4096);
        int mb = m_base + (lane >> 2);
        #pragma unroll
        for (int q = 0; q < 4; q++) wreg[q] = wsm[mb + 8 * q];
    }

    float acc[32];

    // ================= stage A: D = adjI @ Y1g (WZ lower) =================
    gemm2(acc, sb + SM_ADJ, sb + SM_ADJ_LO, sb + SM_WZ, sb + SM_WZ_LO,
          m_base, n_base, lane);
    __syncthreads();       // Y1g fully consumed -> WZ-lower free

    // issue W3-lower into WZ LOWER now; hides under z2-epi + stage B
    #pragma unroll
    for (int i = 0; i < 8; i++) {
        int idx = tid + (i << 8);
        int buf = idx >> 10, rem = idx & 1023;
        const unsigned short* src = (buf ? g_w3_lo : g_w3_hi) + rem * 8;
        cp16(sb + SM_WZ + buf * 32768 + rem * 16, src);
    }
    CP_COMMIT();

    // ---- epi: z2 = relu(D + b2) -> AH (hi/lo) ----
    #pragma unroll
    for (int t = 0; t < 2; t++)
        #pragma unroll
        for (int nt = 0; nt < 4; nt++) {
            float* c = &acc[(t * 4 + nt) * 4];
            int k0 = n_base + nt * 8 + (lane & 3) * 2;
            int m  = m_base + t * 16 + (lane >> 2);
            float b0 = __ldg(bias + 128 + k0);
            float b1 = __ldg(bias + 128 + k0 + 1);
            float v0 = fmaxf(c[0] + b0, 0.0f), v1 = fmaxf(c[1] + b1, 0.0f);
            float v2 = fmaxf(c[2] + b0, 0.0f), v3 = fmaxf(c[3] + b1, 0.0f);
            uint32_t hi2, lo2;
            pack_split(v0, v1, hi2, lo2);
            int off = swz256(m, k0);
            *reinterpret_cast<uint32_t*>(smem + SM_AH + off)    = hi2;
            *reinterpret_cast<uint32_t*>(smem + SM_AH_LO + off) = lo2;
            pack_split(v2, v3, hi2, lo2);
            off = swz256(m + 8, k0);
            *reinterpret_cast<uint32_t*>(smem + SM_AH + off)    = hi2;
            *reinterpret_cast<uint32_t*>(smem + SM_AH_LO + off) = lo2;
        }
    __syncthreads();       // z2 visible

    // ================= stage B: h3 = adjI @ z2 (z2 in AH) =================
    gemm2(acc, sb + SM_ADJ, sb + SM_ADJ_LO, sb + SM_AH, sb + SM_AH_LO,
          m_base, n_base, lane);
    __syncthreads();       // z2 fully consumed

    // ---- epi: h3 -> AH (overwrite z2) ----
    #pragma unroll
    for (int t = 0; t < 2; t++)
        #pragma unroll
        for (int nt = 0; nt < 4; nt++) {
            float* c = &acc[(t * 4 + nt) * 4];
            int d0 = n_base + nt * 8 + (lane & 3) * 2;
            int m  = m_base + t * 16 + (lane >> 2);
            uint32_t hi2, lo2;
            pack_split(c[0], c[1], hi2, lo2);
            int off = swz256(m, d0);
            *reinterpret_cast<uint32_t*>(smem + SM_AH + off)    = hi2;
            *reinterpret_cast<uint32_t*>(smem + SM_AH_LO + off) = lo2;
            pack_split(c[2], c[3], hi2, lo2);
            off = swz256(m + 8, d0);
            *reinterpret_cast<uint32_t*>(smem + SM_AH + off)    = hi2;
            *reinterpret_cast<uint32_t*>(smem + SM_AH_LO + off) = lo2;
        }
    CP_WAIT0();            // W3-lower long since arrived (hidden under stage B)
    __syncthreads();

    // ================= stage C: D3 = h3 @ W3^T =================
    gemm1(acc, sb + SM_AH, sb + SM_AH_LO, sb + SM_WZ, sb + SM_WZ_LO,
          m_base, n_base, lane);
    __syncthreads();       // frees ADJ for pool scratch

    // ---- fused pooled epilogue: out[k] = sum_m w_m * relu(D3[m,k]+b3[k]) ----
    {
        float s[8];
        #pragma unroll
        for (int j = 0; j < 8; j++) s[j] = 0.0f;
        #pragma unroll
        for (int t = 0; t < 2; t++)
            #pragma unroll
            for (int nt = 0; nt < 4; nt++) {
                float* c = &acc[(t * 4 + nt) * 4];
                int k0 = n_base + nt * 8 + (lane & 3) * 2;
                float b0 = __ldg(bias + 256 + k0);
                float b1 = __ldg(bias + 256 + k0 + 1);
                #pragma unroll
                for (int r = 0; r < 4; r++) {
                    float v = fmaxf(c[r] + ((r & 1) ? b1 : b0), 0.0f);
                    s[nt * 2 + (r & 1)] += wreg[t * 2 + (r >> 1)] * v;
                }
            }
        #pragma unroll
        for (int off = 4; off < 32; off <<= 1)
            #pragma unroll
            for (int j = 0; j < 8; j++)
                s[j] += __shfl_xor_sync(0xffffffffu, s[j], off);

        float* pool = reinterpret_cast<float*>(smem + SM_ADJ);   // ADJ dead
        if ((wid & 1) == 0 && (lane >> 2) == 0) {
            #pragma unroll
            for (int nt = 0; nt < 4; nt++) {
                int k = n_base + nt * 8 + (lane & 3) * 2;
                *reinterpret_cast<float2*>(pool + k) = make_float2(s[nt * 2], s[nt * 2 + 1]);
            }
        }
        __syncthreads();
        if ((wid & 1) == 1 && (lane >> 2) == 0) {
            #pragma unroll
            for (int nt = 0; nt < 4; nt++) {
                int k = n_base + nt * 8 + (lane & 3) * 2;
                float2 p = *reinterpret_cast<float2*>(pool + k);
                *reinterpret_cast<float2*>(out + (size_t)bid * 128 + k) =
                    make_float2(p.x + s[nt * 2], p.y + s[nt * 2 + 1]);
            }
        }
    }
}

extern "C" void kernel_launch(void* const* d_in, const int* in_sizes, int n_in,
                              void* d_out, int out_size)
{
    (void)in_sizes; (void)n_in; (void)out_size;
    const int*   fps = (const int*)  d_in[0];
    const float* adj = (const float*)d_in[1];
    const float* emb = (const float*)d_in[2];
    const float* W   = (const float*)d_in[3];
    const float* b   = (const float*)d_in[4];
    float*       out = (float*)d_out;

    cudaFuncSetAttribute(prep_all, cudaFuncAttributeMaxDynamicSharedMemorySize, FP_TOT);
    prep_all<<<192, 256, FP_TOT>>>(emb, W, b);

    cudaFuncSetAttribute(mpnn_main, cudaFuncAttributeMaxDynamicSharedMemorySize, SM_TOTAL);
    mpnn_main<<<4096, 256, SM_TOTAL>>>(fps, adj, b, out);
}

// round 15
// speedup vs baseline: 2.0033x; 2.0033x over previous
#include <cuda_runtime.h>
#include <cuda_fp16.h>
#include <cstdint>

// MPNN, B=4096 graphs, N=64, D=128, L=3. One graph per CTA (M=64), 3 CTAs/SM.
// Algebra (as round 13): Y1 = z1 W2^T per fingerprint (fp32 prologue), then
//   stage A: D = adjI @ Y1g (K=64)   -> z2 = relu(D + b2)
//   stage B: h3 = adjI @ z2 (K=64)
//   stage C: D3 = h3 @ W3^T (K=128)  -> pooled epilogue:
//            out[k] = sum_m w_m relu(D3[m,k]+b3[k]), w = 1 + colsum(adj)
// Precision: SINGLE-PASS fp16 HMMA (fp32 accum). Per-GEMM output error
// ~2e-4 rms from fp16 operand rounding; 3 stages ~3.5e-4 << 1e-3 gate.

__device__ __align__(16) unsigned short g_w3[16384];        // W3 f16 [128r][128c] swizzled
__device__ __align__(16) unsigned short g_y1[2048 * 128];   // Y1 f16 row-major [fp][k]

// ---- main-kernel smem layout (57KB / CTA -> 3 CTAs/SM) ----
#define SM_AH    0        // z2 -> h3, f16 [64][256B] 16KB (colsum scratch at init)
#define SM_WZ    16384    // lower 16KB: Y1g -> W3 rows 0-63 ; upper 16KB: W3 rows 64-127
#define SM_ADJ   49152    // adjI f16 [64][128B] 8KB
#define SM_POOL  57344    // pool scratch (128 floats)
#define SM_TOTAL 57856

// ---- fused-prologue smem layout (fp32 floats) ----
#define FP_SW   0                         // W tile [128][132]
#define FP_SX   (128 * 132)               // in rows [16][132]
#define FP_SZ   (FP_SX + 16 * 132)        // z rows  [16][132]
#define FP_SB   (FP_SZ + 16 * 132)        // bias 128 floats
#define FP_TOT  ((FP_SB + 128) * 4)

__device__ __forceinline__ uint32_t smem_u32(const void* p) {
    uint32_t a;
    asm("{ .reg .u64 t; cvta.to.shared.u64 t, %1; cvt.u32.u64 %0, t; }" : "=r"(a) : "l"(p));
    return a;
}
__device__ __forceinline__ void cp16(uint32_t dst, const void* src) {
    asm volatile("cp.async.cg.shared.global [%0], [%1], 16;" :: "r"(dst), "l"(src));
}
#define CP_COMMIT() asm volatile("cp.async.commit_group;" ::: "memory")
#define CP_WAIT0()  asm volatile("cp.async.wait_group 0;" ::: "memory")

__device__ __forceinline__ void ldsm4(uint32_t* r, uint32_t a) {
    asm volatile("ldmatrix.sync.aligned.m8n8.x4.shared.b16 {%0,%1,%2,%3}, [%4];"
                 : "=r"(r[0]), "=r"(r[1]), "=r"(r[2]), "=r"(r[3]) : "r"(a));
}
__device__ __forceinline__ void ldsm4t(uint32_t* r, uint32_t a) {
    asm volatile("ldmatrix.sync.aligned.m8n8.x4.trans.shared.b16 {%0,%1,%2,%3}, [%4];"
                 : "=r"(r[0]), "=r"(r[1]), "=r"(r[2]), "=r"(r[3]) : "r"(a));
}
__device__ __forceinline__ void mma16816h(float* c, const uint32_t* a, const uint32_t* b) {
    asm volatile("mma.sync.aligned.m16n8k16.row.col.f32.f16.f16.f32 "
                 "{%0,%1,%2,%3}, {%4,%5,%6,%7}, {%8,%9}, {%0,%1,%2,%3};"
                 : "+f"(c[0]), "+f"(c[1]), "+f"(c[2]), "+f"(c[3])
                 : "r"(a[0]), "r"(a[1]), "r"(a[2]), "r"(a[3]), "r"(b[0]), "r"(b[1]));
}
// pack (v0,v1) -> f16x2 with v0 in low half (element order v0, v1)
__device__ __forceinline__ uint32_t f16pack(float v0, float v1) {
    uint32_t r;
    asm("cvt.rn.f16x2.f32 %0, %1, %2;" : "=r"(r) : "f"(v1), "f"(v0));
    return r;
}
// swizzled byte offset, 256B-stride region (16 chunks/row, chunk ^= row&7)
__device__ __forceinline__ int swz256(int row, int col) {
    return (row << 8) + ((((col >> 3) ^ (row & 7)) << 4) | ((col & 7) << 1));
}

// GEMM1: C[64x128] = h[64x128] @ W[128x128]^T ; warp tile 32x32, K=128, fp16 1-pass
__device__ __forceinline__ void gemm1(float (&acc)[32], uint32_t aB, uint32_t bB,
                                      int m_base, int n_base, int lane) {
    #pragma unroll
    for (int i = 0; i < 32; i++) acc[i] = 0.0f;
    const int a_row = lane & 15, a_kc = lane >> 4;
    const int b_row = ((lane >> 4) << 3) + (lane & 7), b_kc = (lane >> 3) & 1;
    #pragma unroll
    for (int ks = 0; ks < 8; ks++) {
        uint32_t aH[2][4];
        #pragma unroll
        for (int t = 0; t < 2; t++) {
            int row = m_base + t * 16 + a_row;
            uint32_t off = (row << 8) + ((((ks << 1) + a_kc) ^ (row & 7)) << 4);
            ldsm4(aH[t], aB + off);
        }
        #pragma unroll
        for (int p = 0; p < 2; p++) {
            int row = n_base + p * 16 + b_row;
            uint32_t off = (row << 8) + ((((ks << 1) + b_kc) ^ (row & 7)) << 4);
            uint32_t bH[4];
            ldsm4(bH, bB + off);
            #pragma unroll
            for (int t = 0; t < 2; t++)
                #pragma unroll
                for (int s = 0; s < 2; s++)
                    mma16816h(&acc[(t * 4 + p * 2 + s) * 4], aH[t], &bH[2 * s]);
        }
    }
}

// GEMM2: C[64x128] = adjI[64x64] @ z[64x128]; A stride 128B, B via ldmatrix.trans
__device__ __forceinline__ void gemm2(float (&acc)[32], uint32_t aB, uint32_t zB,
                                      int m_base, int n_base, int lane) {
    #pragma unroll
    for (int i = 0; i < 32; i++) acc[i] = 0.0f;
    const int a_row = lane & 15, a_kc = lane >> 4;
    const int grp = lane >> 3, r = lane & 7;
    #pragma unroll
    for (int ks = 0; ks < 4; ks++) {
        uint32_t aH[2][4];
        #pragma unroll
        for (int t = 0; t < 2; t++) {
            int row = m_base + t * 16 + a_row;
            uint32_t off = (row << 7) + ((((ks << 1) + a_kc) ^ (row & 7)) << 4);
            ldsm4(aH[t], aB + off);
        }
        int row_b = (ks << 4) + ((grp & 1) << 3) + r;
        #pragma unroll
        for (int p = 0; p < 2; p++) {
            int cc = ((n_base + p * 16) >> 3) + (grp >> 1);
            uint32_t off = (row_b << 8) + ((cc ^ (row_b & 7)) << 4);
            uint32_t bH[4];
            ldsm4t(bH, zB + off);
            #pragma unroll
            for (int t = 0; t < 2; t++)
                #pragma unroll
                for (int s = 0; s < 2; s++)
                    mma16816h(&acc[(t * 4 + p * 2 + s) * 4], aH[t], &bH[2 * s]);
        }
    }
}

// ---------------- fused prologue ----------------
// blocks 0..127:  z1 = relu(emb@W1^T+b1) then Y1 = z1@W2^T (fp32, smem-tiled W),
//                 Y1 written as single fp16.
// blocks 128..191: W3 f16 convert + swizzle.
__global__ __launch_bounds__(256)
void prep_all(const float* __restrict__ emb, const float* __restrict__ W,
              const float* __restrict__ bias) {
    const int tid = threadIdx.x;
    if (blockIdx.x >= 128) {
        int idx = (int)(blockIdx.x - 128) * 256 + tid;   // 0..16383
        int row = idx >> 7, col = idx & 127;
        float v = W[2 * 16384 + idx];
        int pos = row * 128 + (((col >> 3) ^ (row & 7)) << 3) + (col & 7);
        g_w3[pos] = __half_as_ushort(__float2half_rn(v));
        return;
    }

    extern __shared__ float fsm[];
    float* sW = fsm + FP_SW;
    float* sX = fsm + FP_SX;
    float* sZ = fsm + FP_SZ;
    float* sB = fsm + FP_SB;
    const int tx = tid & 31, ty = tid >> 5;
    const int r0 = (int)blockIdx.x * 16;

    const float4* W4 = reinterpret_cast<const float4*>(W);
    #pragma unroll
    for (int i = 0; i < 16; i++) {
        int q = tid + (i << 8);
        int k = q >> 5, c4 = (q & 31) << 2;
        *reinterpret_cast<float4*>(&sW[k * 132 + c4]) = __ldg(W4 + q);
    }
    const float4* E4 = reinterpret_cast<const float4*>(emb);
    #pragma unroll
    for (int i = 0; i < 2; i++) {
        int q = tid + (i << 8);
        int r = q >> 5, c4 = (q & 31) << 2;
        *reinterpret_cast<float4*>(&sX[r * 132 + c4]) =
            __ldg(E4 + (size_t)(r0 + r) * 32 + (q & 31));
    }
    if (tid < 128) sB[tid] = bias[tid];
    __syncthreads();

    float acc[2][4];
    #pragma unroll
    for (int i = 0; i < 2; i++)
        #pragma unroll
        for (int j = 0; j < 4; j++) acc[i][j] = 0.0f;
    for (int d4 = 0; d4 < 32; d4++) {
        float4 wv[4], ev[2];
        #pragma unroll
        for (int j = 0; j < 4; j++)
            wv[j] = *reinterpret_cast<const float4*>(&sW[(tx + 32 * j) * 132 + (d4 << 2)]);
        #pragma unroll
        for (int i = 0; i < 2; i++)
            ev[i] = *reinterpret_cast<const float4*>(&sX[(ty * 2 + i) * 132 + (d4 << 2)]);
        #pragma unroll
        for (int i = 0; i < 2; i++)
            #pragma unroll
            for (int j = 0; j < 4; j++) {
                acc[i][j] = fmaf(ev[i].x, wv[j].x, acc[i][j]);
                acc[i][j] = fmaf(ev[i].y, wv[j].y, acc[i][j]);
                acc[i][j] = fmaf(ev[i].z, wv[j].z, acc[i][j]);
                acc[i][j] = fmaf(ev[i].w, wv[j].w, acc[i][j]);
            }
    }
    #pragma unroll
    for (int i = 0; i < 2; i++)
        #pragma unroll
        for (int j = 0; j < 4; j++) {
            int k = tx + 32 * j;
            sZ[(ty * 2 + i) * 132 + k] = fmaxf(acc[i][j] + sB[k], 0.0f);
        }
    __syncthreads();

    #pragma unroll
    for (int i = 0; i < 16; i++) {
        int q = tid + (i << 8);
        int k = q >> 5, c4 = (q & 31) << 2;
        *reinterpret_cast<float4*>(&sW[k * 132 + c4]) = __ldg(W4 + 4096 + q);
    }
    __syncthreads();

    #pragma unroll
    for (int i = 0; i < 2; i++)
        #pragma unroll
        for (int j = 0; j < 4; j++) acc[i][j] = 0.0f;
    for (int d4 = 0; d4 < 32; d4++) {
        float4 wv[4], ev[2];
        #pragma unroll
        for (int j = 0; j < 4; j++)
            wv[j] = *reinterpret_cast<const float4*>(&sW[(tx + 32 * j) * 132 + (d4 << 2)]);
        #pragma unroll
        for (int i = 0; i < 2; i++)
            ev[i] = *reinterpret_cast<const float4*>(&sZ[(ty * 2 + i) * 132 + (d4 << 2)]);
        #pragma unroll
        for (int i = 0; i < 2; i++)
            #pragma unroll
            for (int j = 0; j < 4; j++) {
                acc[i][j] = fmaf(ev[i].x, wv[j].x, acc[i][j]);
                acc[i][j] = fmaf(ev[i].y, wv[j].y, acc[i][j]);
                acc[i][j] = fmaf(ev[i].z, wv[j].z, acc[i][j]);
                acc[i][j] = fmaf(ev[i].w, wv[j].w, acc[i][j]);
            }
    }
    #pragma unroll
    for (int i = 0; i < 2; i++)
        #pragma unroll
        for (int j = 0; j < 4; j++) {
            int r = r0 + ty * 2 + i;
            int k = tx + 32 * j;
            g_y1[r * 128 + k] = __half_as_ushort(__float2half_rn(acc[i][j]));
        }
}

// ---------------- main kernel (fp16 single-pass) ----------------
__global__ __launch_bounds__(256, 3)
void mpnn_main(const int* __restrict__ fps,
               const float* __restrict__ adj,
               const float* __restrict__ bias,
               float* __restrict__ out)
{
    extern __shared__ char smem[];
    const uint32_t sb = smem_u32(smem);
    const int tid = threadIdx.x, wid = tid >> 5, lane = tid & 31;
    const int bid = blockIdx.x;
    const int m_base = (wid & 1) << 5;     // 0 / 32
    const int n_base = (wid >> 1) << 5;    // 0,32,64,96

    // ---- issue Y1 gather into WZ LOWER + W3 rows 64-127 into WZ UPPER ----
    #pragma unroll
    for (int i = 0; i < 4; i++) {
        int idx = tid + (i << 8);                  // 0..1023 (Y1g: 64 rows x 16 chunks)
        int m = idx >> 4, c = idx & 15;
        int fp = fps[(bid << 6) + m];
        const unsigned short* src = g_y1 + (size_t)fp * 128 + c * 8;
        cp16(sb + SM_WZ + (m << 8) + ((c ^ (m & 7)) << 4), src);
    }
    #pragma unroll
    for (int i = 0; i < 4; i++) {
        int idx = tid + (i << 8);                  // 0..1023 (W3 rows 64-127, 16KB)
        const unsigned short* src = g_w3 + 8192 + idx * 8;
        cp16(sb + SM_WZ + 16384 + idx * 16, src);
    }
    CP_COMMIT();

    // ---- adjI = I + adj: f16 convert + swizzled STS + column-sum partials ----
    float4 s4 = make_float4(0.f, 0.f, 0.f, 0.f);
    {
        const float4* ag = reinterpret_cast<const float4*>(adj) + (size_t)bid * 1024;
        #pragma unroll
        for (int i = 0; i < 4; i++) {
            int q   = tid + (i << 8);              // float4 idx 0..1023
            int row = q >> 4;
            int c4  = (q & 15) << 2;
            float4 v = ag[q];
            float a0 = v.x + ((row == c4 + 0) ? 1.0f : 0.0f);
            float a1 = v.y + ((row == c4 + 1) ? 1.0f : 0.0f);
            float a2 = v.z + ((row == c4 + 2) ? 1.0f : 0.0f);
            float a3 = v.w + ((row == c4 + 3) ? 1.0f : 0.0f);
            s4.x += a0; s4.y += a1; s4.z += a2; s4.w += a3;
            int off = (row << 7) + ((((c4 >> 3) ^ (row & 7)) << 4) | ((c4 & 7) << 1));
            *reinterpret_cast<uint32_t*>(smem + SM_ADJ + off)     = f16pack(a0, a1);
            *reinterpret_cast<uint32_t*>(smem + SM_ADJ + off + 4) = f16pack(a2, a3);
        }
    }
    {   // colsum partials -> AH scratch (AH dead until z2 epilogue)
        float4* part = reinterpret_cast<float4*>(smem + SM_AH);
        part[tid] = s4;
    }
    __syncthreads();
    if (tid < 16) {
        float4* part = reinterpret_cast<float4*>(smem + SM_AH);
        float4 cs = part[tid];
        #pragma unroll
        for (int j = 1; j < 16; j++) {
            float4 p = part[tid + 16 * j];
            cs.x += p.x; cs.y += p.y; cs.z += p.z; cs.w += p.w;
        }
        *reinterpret_cast<float4*>(smem + SM_AH + 4096 + tid * 16) = cs;
    }
    CP_WAIT0();            // Y1g + W3-upper arrived
    __syncthreads();

    // cache pooling weights w[m] = 1 + colsum(adj)[m]
    float wreg[4];
    {
        const float* wsm = reinterpret_cast<const float*>(smem + SM_AH + 4096);
        int mb = m_base + (lane >> 2);
        #pragma unroll
        for (int q = 0; q < 4; q++) wreg[q] = wsm[mb + 8 * q];
    }

    float acc[32];

    // ================= stage A: D = adjI @ Y1g (WZ lower) =================
    gemm2(acc, sb + SM_ADJ, sb + SM_WZ, m_base, n_base, lane);
    __syncthreads();       // Y1g consumed + wreg reads done before AH/WZ overwritten

    // issue W3 rows 0-63 into WZ LOWER; hides under z2-epi + stage B
    #pragma unroll
    for (int i = 0; i < 4; i++) {
        int idx = tid + (i << 8);                  // 0..1023
        const unsigned short* src = g_w3 + idx * 8;
        cp16(sb + SM_WZ + idx * 16, src);
    }
    CP_COMMIT();

    // ---- epi: z2 = relu(D + b2) -> AH (f16) ----
    #pragma unroll
    for (int t = 0; t < 2; t++)
        #pragma unroll
        for (int nt = 0; nt < 4; nt++) {
            float* c = &acc[(t * 4 + nt) * 4];
            int k0 = n_base + nt * 8 + (lane & 3) * 2;
            int m  = m_base + t * 16 + (lane >> 2);
            float b0 = __ldg(bias + 128 + k0);
            float b1 = __ldg(bias + 128 + k0 + 1);
            *reinterpret_cast<uint32_t*>(smem + SM_AH + swz256(m, k0)) =
                f16pack(fmaxf(c[0] + b0, 0.0f), fmaxf(c[1] + b1, 0.0f));
            *reinterpret_cast<uint32_t*>(smem + SM_AH + swz256(m + 8, k0)) =
                f16pack(fmaxf(c[2] + b0, 0.0f), fmaxf(c[3] + b1, 0.0f));
        }
    __syncthreads();       // z2 visible

    // ================= stage B: h3 = adjI @ z2 (z2 in AH) =================
    gemm2(acc, sb + SM_ADJ, sb + SM_AH, m_base, n_base, lane);
    __syncthreads();       // z2 fully consumed

    // ---- epi: h3 -> AH (overwrite z2) ----
    #pragma unroll
    for (int t = 0; t < 2; t++)
        #pragma unroll
        for (int nt = 0; nt < 4; nt++) {
            float* c = &acc[(t * 4 + nt) * 4];
            int d0 = n_base + nt * 8 + (lane & 3) * 2;
            int m  = m_base + t * 16 + (lane >> 2);
            *reinterpret_cast<uint32_t*>(smem + SM_AH + swz256(m, d0)) =
                f16pack(c[0], c[1]);
            *reinterpret_cast<uint32_t*>(smem + SM_AH + swz256(m + 8, d0)) =
                f16pack(c[2], c[3]);
        }
    CP_WAIT0();            // W3-lower arrived (hidden under stage B)
    __syncthreads();

    // ================= stage C: D3 = h3 @ W3^T =================
    gemm1(acc, sb + SM_AH, sb + SM_WZ, m_base, n_base, lane);
    __syncthreads();       // all reads done; pool scratch free

    // ---- fused pooled epilogue: out[k] = sum_m w_m * relu(D3[m,k]+b3[k]) ----
    {
        float s[8];
        #pragma unroll
        for (int j = 0; j < 8; j++) s[j] = 0.0f;
        #pragma unroll
        for (int t = 0; t < 2; t++)
            #pragma unroll
            for (int nt = 0; nt < 4; nt++) {
                float* c = &acc[(t * 4 + nt) * 4];
                int k0 = n_base + nt * 8 + (lane & 3) * 2;
                float b0 = __ldg(bias + 256 + k0);
                float b1 = __ldg(bias + 256 + k0 + 1);
                #pragma unroll
                for (int r = 0; r < 4; r++) {
                    float v = fmaxf(c[r] + ((r & 1) ? b1 : b0), 0.0f);
                    s[nt * 2 + (r & 1)] += wreg[t * 2 + (r >> 1)] * v;
                }
            }
        #pragma unroll
        for (int off = 4; off < 32; off <<= 1)
            #pragma unroll
            for (int j = 0; j < 8; j++)
                s[j] += __shfl_xor_sync(0xffffffffu, s[j], off);

        float* pool = reinterpret_cast<float*>(smem + SM_POOL);
        if ((wid & 1) == 0 && (lane >> 2) == 0) {
            #pragma unroll
            for (int nt = 0; nt < 4; nt++) {
                int k = n_base + nt * 8 + (lane & 3) * 2;
                *reinterpret_cast<float2*>(pool + k) = make_float2(s[nt * 2], s[nt * 2 + 1]);
            }
        }
        __syncthreads();
        if ((wid & 1) == 1 && (lane >> 2) == 0) {
            #pragma unroll
            for (int nt = 0; nt < 4; nt++) {
                int k = n_base + nt * 8 + (lane & 3) * 2;
                float2 p = *reinterpret_cast<float2*>(pool + k);
                *reinterpret_cast<float2*>(out + (size_t)bid * 128 + k) =
                    make_float2(p.x + s[nt * 2], p.y + s[nt * 2 + 1]);
            }
        }
    }
}

extern "C" void kernel_launch(void* const* d_in, const int* in_sizes, int n_in,
                              void* d_out, int out_size)
{
    (void)in_sizes; (void)n_in; (void)out_size;
    const int*   fps = (const int*)  d_in[0];
    const float* adj = (const float*)d_in[1];
    const float* emb = (const float*)d_in[2];
    const float* W   = (const float*)d_in[3];
    const float* b   = (const float*)d_in[4];
    float*       out = (float*)d_out;

    cudaFuncSetAttribute(prep_all, cudaFuncAttributeMaxDynamicSharedMemorySize, FP_TOT);
    prep_all<<<192, 256, FP_TOT>>>(emb, W, b);

    cudaFuncSetAttribute(mpnn_main, cudaFuncAttributeMaxDynamicSharedMemorySize, SM_TOTAL);
    mpnn_main<<<4096, 256, SM_TOTAL>>>(fps, adj, b, out);
}